// round 14
// baseline (speedup 1.0000x reference)
#include <cuda_runtime.h>
#include <cuda_fp16.h>
#include <cstdint>

#define MAX_N 50000
#define MAX_E 800000

// ---------------- device scratch (no allocation allowed) -------------------
// g_Yh row layout (1024 halfs): [Y0 | Y3 | Y1 | Y2]
//   fwd edge: Y0[f] + Y1[t];  rev edge: Y2[t] + Y3[f]   (biases folded)
__device__ __half g_Yh[(size_t)MAX_N * 1024];  // 102.4 MB, fits L2
__device__ float  g_agg[(size_t)MAX_N * 256];  // [N][256] aggregation
__device__ __half g_w2[2][65536];              // [dir][n*256+k] fp16 W2
// CSR scatter machinery
__device__ int    g_cnt[MAX_N];
__device__ int    g_off[MAX_N + 1];
__device__ int    g_cur[MAX_N];
__device__ int    g_perm[2 * MAX_E];
__device__ __half g_msg[(size_t)2 * MAX_E * 256];   // 819 MB message rows

// ---------------- small asm helpers ----------------------------------------
__device__ __forceinline__ uint32_t smem_u32(const void* p) {
    uint32_t a;
    asm("{ .reg .u64 t; cvta.to.shared.u64 t, %1; cvt.u32.u64 %0, t; }" : "=r"(a) : "l"(p));
    return a;
}
__device__ __forceinline__ void cpa16(uint32_t dst, const void* src) {
    asm volatile("cp.async.cg.shared.global [%0], [%1], 16;" :: "r"(dst), "l"(src));
}
#define CP_COMMIT() asm volatile("cp.async.commit_group;" ::: "memory")
#define CP_WAIT(n)  asm volatile("cp.async.wait_group %0;" :: "n"(n) : "memory")

__device__ __forceinline__ void ldsm4(uint32_t* r, uint32_t addr) {
    asm volatile("ldmatrix.sync.aligned.m8n8.x4.shared.b16 {%0,%1,%2,%3}, [%4];"
                 : "=r"(r[0]), "=r"(r[1]), "=r"(r[2]), "=r"(r[3]) : "r"(addr));
}
__device__ __forceinline__ void ldsm2(uint32_t* r, uint32_t addr) {
    asm volatile("ldmatrix.sync.aligned.m8n8.x2.shared.b16 {%0,%1}, [%2];"
                 : "=r"(r[0]), "=r"(r[1]) : "r"(addr));
}
__device__ __forceinline__ void mma16816(float* c, const uint32_t* a, const uint32_t* b) {
    asm volatile("mma.sync.aligned.m16n8k16.row.col.f32.f16.f16.f32 "
                 "{%0,%1,%2,%3}, {%4,%5,%6,%7}, {%8,%9}, {%0,%1,%2,%3};"
                 : "+f"(c[0]), "+f"(c[1]), "+f"(c[2]), "+f"(c[3])
                 : "r"(a[0]), "r"(a[1]), "r"(a[2]), "r"(a[3]), "r"(b[0]), "r"(b[1]));
}
__device__ __forceinline__ float2 h2f(uint32_t u) {
    __half2 h = *reinterpret_cast<__half2*>(&u);
    return __half22float2(h);
}
__device__ __forceinline__ uint32_t f2h(float a, float b) {
    __half2 h = __floats2half2_rn(a, b);
    return *reinterpret_cast<uint32_t*>(&h);
}

// ---------------- edge-kernel smem layout (byte offsets) --------------------
#define SH    0            // [128 rows][264 halfs] hidden (stride 528B) = 67,584B
#define SWB   67584        // 2 stages x [256 n][40 halfs] = 2 x 20,480B -> 108,544
#define SBIAS 108544       // 256 f32
#define SWEF  109568       // 256 f32
#define SEF   110592       // 128 f32
#define ESMEM 111104

// ---------------- CSR prologue kernels ---------------------------------------
__global__ void zero_cnt_kernel(int N) {
    int i = blockIdx.x * blockDim.x + threadIdx.x;
    if (i < N) g_cnt[i] = 0;
}
__global__ void hist_kernel(const int* __restrict__ to, const int* __restrict__ from, int E) {
    int i = blockIdx.x * blockDim.x + threadIdx.x;
    if (i < 2 * E) {
        int dst = (i < E) ? to[i] : from[i - E];
        atomicAdd(&g_cnt[dst], 1);
    }
}
__global__ void scan_kernel(int N) {
    __shared__ int buf[1024];
    __shared__ int s_carry;
    if (threadIdx.x == 0) s_carry = 0;
    __syncthreads();
    for (int base = 0; base < N; base += 1024) {
        int i = base + threadIdx.x;
        int v = (i < N) ? g_cnt[i] : 0;
        buf[threadIdx.x] = v;
        __syncthreads();
        for (int ofs = 1; ofs < 1024; ofs <<= 1) {
            int y = 0;
            if (threadIdx.x >= ofs) y = buf[threadIdx.x - ofs];
            __syncthreads();
            buf[threadIdx.x] += y;
            __syncthreads();
        }
        int incl = buf[threadIdx.x];
        int c = s_carry;
        if (i < N) {
            int ex = c + incl - v;
            g_off[i] = ex;
            g_cur[i] = ex;
        }
        __syncthreads();
        if (threadIdx.x == 0) s_carry = c + buf[1023];
        __syncthreads();
    }
    if (threadIdx.x == 0) g_off[N] = s_carry;
}
__global__ void perm_kernel(const int* __restrict__ to, const int* __restrict__ from, int E) {
    int i = blockIdx.x * blockDim.x + threadIdx.x;
    if (i < 2 * E) {
        int dst = (i < E) ? to[i] : from[i - E];
        g_perm[i] = atomicAdd(&g_cur[dst], 1);
    }
}

// ---------------- prep: W2 transpose + fp16 round ---------------------------
__global__ void prep_w_kernel(const float* __restrict__ W, __half* __restrict__ oh) {
    int i = blockIdx.x * 256 + threadIdx.x;      // i = n*256 + k
    if (i >= 65536) return;
    int n = i >> 8, k = i & 255;
    oh[i] = __float2half_rn(W[k * 256 + n]);
}

// ---------------- node-level L1 precompute (exact fp32 FFMA -> fp16) --------
// Proven 256-thread / 8x8-tile version (R11).
__global__ __launch_bounds__(256, 1)
void precompute_y(const float* __restrict__ ns,
                  const float* __restrict__ W1, const float* __restrict__ RW1,
                  const float* __restrict__ b1, const float* __restrict__ Rb1, int N)
{
    extern __shared__ float sm[];
    float* sS = sm;           // 64*128
    float* sW = sm + 8192;    // 32*256
    const int tid = threadIdx.x;
    const int n0 = blockIdx.x * 64;

    for (int t = tid; t < 64 * 32; t += 256) {
        int n = t >> 5, c = t & 31;
        float4 v = make_float4(0.f, 0.f, 0.f, 0.f);
        if (n0 + n < N)
            v = reinterpret_cast<const float4*>(ns)[(size_t)(n0 + n) * 32 + c];
        reinterpret_cast<float4*>(sS)[t] = v;
    }

    const int wg = tid >> 5, lane = tid & 31;
    const int nb = wg * 8, j0 = lane * 8;

    for (int q = 0; q < 4; ++q) {
        const float* Wsrc = (q < 2) ? W1 : RW1;
        const int rowoff = (q & 1) * 128;
        const int seg = (q == 0) ? 0 : (q == 1) ? 2 : (q == 2) ? 3 : 1;
        float acc[8][8];
        #pragma unroll
        for (int jj = 0; jj < 8; ++jj) {
            float bv = (q == 1) ? b1[j0 + jj] : ((q == 3) ? Rb1[j0 + jj] : 0.f);
            #pragma unroll
            for (int ii = 0; ii < 8; ++ii) acc[ii][jj] = bv;
        }
        for (int kt = 0; kt < 4; ++kt) {
            __syncthreads();
            {
                const float4* src = reinterpret_cast<const float4*>(Wsrc + (rowoff + kt * 32) * 256);
                float4* dw = reinterpret_cast<float4*>(sW);
                #pragma unroll
                for (int t0 = 0; t0 < 8; ++t0) dw[tid + t0 * 256] = src[tid + t0 * 256];
            }
            __syncthreads();
            #pragma unroll 8
            for (int kk = 0; kk < 32; ++kk) {
                float xv[8];
                #pragma unroll
                for (int ii = 0; ii < 8; ++ii) xv[ii] = sS[(nb + ii) * 128 + kt * 32 + kk];
                float4 w0 = *reinterpret_cast<const float4*>(&sW[kk * 256 + j0]);
                float4 w1 = *reinterpret_cast<const float4*>(&sW[kk * 256 + j0 + 4]);
                float wv[8] = {w0.x, w0.y, w0.z, w0.w, w1.x, w1.y, w1.z, w1.w};
                #pragma unroll
                for (int ii = 0; ii < 8; ++ii)
                    #pragma unroll
                    for (int jj = 0; jj < 8; ++jj)
                        acc[ii][jj] = fmaf(xv[ii], wv[jj], acc[ii][jj]);
            }
        }
        #pragma unroll
        for (int ii = 0; ii < 8; ++ii) {
            int n = n0 + nb + ii;
            if (n < N) {
                uint4 pk;
                pk.x = f2h(acc[ii][0], acc[ii][1]);
                pk.y = f2h(acc[ii][2], acc[ii][3]);
                pk.z = f2h(acc[ii][4], acc[ii][5]);
                pk.w = f2h(acc[ii][6], acc[ii][7]);
                *reinterpret_cast<uint4*>(g_Yh + (size_t)n * 1024 + seg * 256 + j0) = pk;
            }
        }
    }
}

// ---------------- L2 GEMM: single-term fp16, M=128, warp tile 32x64 ---------
__device__ __forceinline__ void gemm_l2(const __half* __restrict__ gw,
                                        uint32_t smb, int tid,
                                        uint32_t aB0, uint32_t aB1, uint32_t bB,
                                        float acc0[8][4], float acc1[8][4])
{
    auto copy_chunk = [&](int s, int c) {
        #pragma unroll
        for (int i = 0; i < 2; ++i) {
            int idx = i * 512 + tid;
            int n = idx >> 2, seg = idx & 3;
            const __half* src = gw + n * 256 + c * 32 + seg * 8;
            uint32_t dst = smb + SWB + (uint32_t)(s * 20480 + n * 80 + seg * 16);
            cpa16(dst, src);
        }
    };

    copy_chunk(0, 0);
    CP_COMMIT();
    for (int c = 0; c < 8; ++c) {
        const int s = c & 1;
        if (c < 7) { copy_chunk(s ^ 1, c + 1); CP_COMMIT(); CP_WAIT(1); }
        else       { CP_WAIT(0); }
        __syncthreads();
        #pragma unroll
        for (int ks = 0; ks < 2; ++ks) {
            const int step = c * 2 + ks;
            const uint32_t coloff = ((step < 8) ? 0u : 256u) + (step & 7) * 32;
            uint32_t A0[4], A1[4];
            ldsm4(A0, aB0 + coloff);
            ldsm4(A1, aB1 + coloff);
            const uint32_t wrow = smb + SWB + (uint32_t)(s * 20480) + bB + ks * 32;
            #pragma unroll
            for (int nf = 0; nf < 8; ++nf) {
                uint32_t Bh[2];
                ldsm2(Bh, wrow + nf * 640);
                mma16816(acc0[nf], A0, Bh);
                mma16816(acc1[nf], A1, Bh);
            }
        }
        __syncthreads();
    }
}

// ---------------- edge kernel: 128 edges/CTA, combine + MMA + CSR store -----
__global__ __launch_bounds__(512, 1)
void edge_mma_kernel(const float* __restrict__ ef,
                     const int* __restrict__ fidx, const int* __restrict__ tidx,
                     const float* __restrict__ W1, const float* __restrict__ RW1,
                     const float* __restrict__ b2, const float* __restrict__ Rb2,
                     int E)
{
    extern __shared__ float smf[];
    char* smc = reinterpret_cast<char*>(smf);
    const uint32_t smb = smem_u32(smf);
    const int tid = threadIdx.x;
    const int wid = tid >> 5, lane = tid & 31;
    const int wm = wid & 3, wn = wid >> 2;       // 4 m-warps x 4 n-warps
    const int m0 = wm * 32, n0 = wn * 64;        // warp tile 32 x 64
    const int e0 = blockIdx.x * 128;

    float* sBias = reinterpret_cast<float*>(smc + SBIAS);
    float* sWef  = reinterpret_cast<float*>(smc + SWEF);
    float* sEf   = reinterpret_cast<float*>(smc + SEF);

    if (tid < 128) sEf[tid] = (e0 + tid < E) ? ef[e0 + tid] : 0.f;

    // lane-resolved fragment addresses (A from sH, stride 264 halfs)
    const int rA = (lane & 7) + ((lane >> 3) & 1) * 8;
    const int cAo = (lane >> 4) * 8;
    const uint32_t aB0 = smb + SH + (uint32_t)((m0 + rA) * 528 + cAo * 2);
    const uint32_t aB1 = aB0 + 16 * 528;         // +16 rows
    const uint32_t bB = (uint32_t)(((n0 + (lane & 7)) * 40 + ((lane >> 3) & 1) * 8) * 2);
    const int r0 = m0 + (lane >> 2);

    // combine/store-phase indices: 128 rows x 4 col-quarters (64 halfs each)
    const int crow = tid >> 2, cq = tid & 3;
    int ce = e0 + crow; if (ce >= E) ce = E - 1;
    const int cf = fidx[ce], ct = tidx[ce];

    for (int dir = 0; dir < 2; ++dir) {
        const float* bias2 = dir ? Rb2 : b2;
        const float* wef = (dir ? RW1 : W1) + 65536;    // W1 row k=256 (ef col)
        const __half* gw = g_w2[dir];

        __syncthreads();                          // prior dir's smem readers done
        if (tid < 256) {
            sBias[tid] = bias2[tid];
            sWef[tid]  = wef[tid];
        }
        __syncthreads();

        // ---- L1 combine: h = relu(Ya + Yb + ef*wef) from fp16 g_Yh -> sH ----
        {
            const __half* Ap;
            const __half* Bp;
            if (dir == 0) {   // fwd: Y0[f] + Y1[t]
                Ap = g_Yh + (size_t)cf * 1024 + cq * 64;
                Bp = g_Yh + (size_t)ct * 1024 + 512 + cq * 64;
            } else {          // rev: Y2[t] + Y3[f]
                Ap = g_Yh + (size_t)ct * 1024 + 768 + cq * 64;
                Bp = g_Yh + (size_t)cf * 1024 + 256 + cq * 64;
            }
            const float efv = sEf[crow];
            const uint4* A4 = reinterpret_cast<const uint4*>(Ap);
            const uint4* B4 = reinterpret_cast<const uint4*>(Bp);
            #pragma unroll
            for (int i = 0; i < 8; ++i) {
                uint4 ua = A4[i], ub = B4[i];
                const int cb = cq * 64 + i * 8;
                float2 w0 = *reinterpret_cast<const float2*>(&sWef[cb]);
                float2 w1 = *reinterpret_cast<const float2*>(&sWef[cb + 2]);
                float2 w2 = *reinterpret_cast<const float2*>(&sWef[cb + 4]);
                float2 w3 = *reinterpret_cast<const float2*>(&sWef[cb + 6]);
                float2 a0 = h2f(ua.x), b0 = h2f(ub.x);
                float2 a1 = h2f(ua.y), b1v = h2f(ub.y);
                float2 a2 = h2f(ua.z), b2v = h2f(ub.z);
                float2 a3 = h2f(ua.w), b3v = h2f(ub.w);
                uint4 pk;
                pk.x = f2h(fmaxf(a0.x + b0.x + efv * w0.x, 0.f),
                           fmaxf(a0.y + b0.y + efv * w0.y, 0.f));
                pk.y = f2h(fmaxf(a1.x + b1v.x + efv * w1.x, 0.f),
                           fmaxf(a1.y + b1v.y + efv * w1.y, 0.f));
                pk.z = f2h(fmaxf(a2.x + b2v.x + efv * w2.x, 0.f),
                           fmaxf(a2.y + b2v.y + efv * w2.y, 0.f));
                pk.w = f2h(fmaxf(a3.x + b3v.x + efv * w3.x, 0.f),
                           fmaxf(a3.y + b3v.y + efv * w3.y, 0.f));
                *reinterpret_cast<uint4*>(smc + SH + crow * 528 + cb * 2) = pk;
            }
        }
        __syncthreads();                          // sH visible to ldmatrix

        // ---- L2: msg = h @ W2 + b2 (single-term fp16 HMMA) ------------------
        float acc0[8][4], acc1[8][4];
        #pragma unroll
        for (int nf = 0; nf < 8; ++nf) {
            int cc = n0 + nf * 8 + (lane & 3) * 2;
            float bv0 = sBias[cc], bv1 = sBias[cc + 1];
            acc0[nf][0] = bv0; acc0[nf][1] = bv1;
            acc0[nf][2] = bv0; acc0[nf][3] = bv1;
            acc1[nf][0] = bv0; acc1[nf][1] = bv1;
            acc1[nf][2] = bv0; acc1[nf][3] = bv1;
        }
        gemm_l2(gw, smb, tid, aB0, aB1, bB, acc0, acc1);
        // gemm ends with __syncthreads: all sH reads done -> safe to overwrite

        // ---- stage msg tile to sH as fp16 -----------------------------------
        #pragma unroll
        for (int nf = 0; nf < 8; ++nf) {
            int cc = n0 + nf * 8 + (lane & 3) * 2;
            *reinterpret_cast<uint32_t*>(smc + SH + (r0 * 264 + cc) * 2) =
                f2h(acc0[nf][0], acc0[nf][1]);
            *reinterpret_cast<uint32_t*>(smc + SH + ((r0 + 8) * 264 + cc) * 2) =
                f2h(acc0[nf][2], acc0[nf][3]);
            *reinterpret_cast<uint32_t*>(smc + SH + ((r0 + 16) * 264 + cc) * 2) =
                f2h(acc1[nf][0], acc1[nf][1]);
            *reinterpret_cast<uint32_t*>(smc + SH + ((r0 + 24) * 264 + cc) * 2) =
                f2h(acc1[nf][2], acc1[nf][3]);
        }
        __syncthreads();

        // ---- write msg rows to CSR slots (coalesced 128B per thread) --------
        {
            const int er = e0 + crow;
            if (er < E) {
                int p = g_perm[(size_t)dir * E + er];
                uint4* dst = reinterpret_cast<uint4*>(g_msg + (size_t)p * 256 + cq * 64);
                const uint4* src = reinterpret_cast<const uint4*>(smc + SH + crow * 528 + cq * 128);
                #pragma unroll
                for (int u = 0; u < 8; ++u) dst[u] = src[u];
            }
        }
    }
}

// ---------------- gather: CSR row-range sum -> g_agg (fp32) -----------------
__global__ __launch_bounds__(512, 1)
void gather_kernel(int N) {
    const int tid = threadIdx.x;
    const int n = blockIdx.x * 64 + (tid >> 3);
    const int q = tid & 7;                      // 8 segments of 32 halfs (64B)
    if (n >= N) return;
    const int beg = g_off[n], end = g_off[n + 1];
    float acc[32];
    #pragma unroll
    for (int j = 0; j < 32; ++j) acc[j] = 0.f;
    for (int r = beg; r < end; ++r) {
        const uint4* src = reinterpret_cast<const uint4*>(g_msg + (size_t)r * 256 + q * 32);
        #pragma unroll
        for (int u = 0; u < 4; ++u) {
            uint4 v = src[u];
            float2 f0 = h2f(v.x), f1 = h2f(v.y), f2 = h2f(v.z), f3 = h2f(v.w);
            acc[u * 8 + 0] += f0.x; acc[u * 8 + 1] += f0.y;
            acc[u * 8 + 2] += f1.x; acc[u * 8 + 3] += f1.y;
            acc[u * 8 + 4] += f2.x; acc[u * 8 + 5] += f2.y;
            acc[u * 8 + 6] += f3.x; acc[u * 8 + 7] += f3.y;
        }
    }
    float4* dst = reinterpret_cast<float4*>(g_agg + (size_t)n * 256 + q * 32);
    #pragma unroll
    for (int u = 0; u < 8; ++u)
        dst[u] = make_float4(acc[u * 4], acc[u * 4 + 1], acc[u * 4 + 2], acc[u * 4 + 3]);
}

// ---------------- node update MLP + residual (FFMA, proven 256-thr) --------
__global__ __launch_bounds__(256, 1)
void node_kernel(const float* __restrict__ node_states,
                 const float* __restrict__ Wn1, const float* __restrict__ bn1,
                 const float* __restrict__ Wn2, const float* __restrict__ bn2,
                 float* __restrict__ out, int N)
{
    extern __shared__ float sm[];
    float* sA = sm;            // 64*256
    float* sS = sm + 16384;    // 64*128
    float* sH = sm + 24576;    // 64*256
    float* sW = sm + 40960;    // 32*256

    const int tid = threadIdx.x;
    const int n0  = blockIdx.x * 64;

    for (int t = tid; t < 64 * 64; t += 256) {
        int n = t >> 6, c = t & 63;
        float4 v = make_float4(0.f, 0.f, 0.f, 0.f);
        if (n0 + n < N)
            v = reinterpret_cast<const float4*>(g_agg)[(size_t)(n0 + n) * 64 + c];
        reinterpret_cast<float4*>(sA)[t] = v;
    }
    for (int t = tid; t < 64 * 32; t += 256) {
        int n = t >> 5, c = t & 31;
        float4 v = make_float4(0.f, 0.f, 0.f, 0.f);
        if (n0 + n < N)
            v = reinterpret_cast<const float4*>(node_states)[(size_t)(n0 + n) * 32 + c];
        reinterpret_cast<float4*>(sS)[t] = v;
    }
    __syncthreads();

    const int wg = tid >> 5, lane = tid & 31;
    const int nBase = wg * 8, j0 = lane * 8;

    float acc[8][8];
    #pragma unroll
    for (int jj = 0; jj < 8; ++jj) {
        float bv = bn1[j0 + jj];
        #pragma unroll
        for (int ii = 0; ii < 8; ++ii) acc[ii][jj] = bv;
    }
    for (int kt = 0; kt < 12; ++kt) {
        __syncthreads();
        {
            const float4* src = reinterpret_cast<const float4*>(Wn1 + kt * 32 * 256);
            float4* dw = reinterpret_cast<float4*>(sW);
            #pragma unroll
            for (int t0 = 0; t0 < 8; ++t0) dw[tid + t0 * 256] = src[tid + t0 * 256];
        }
        __syncthreads();
        const float* Xb; int strd;
        if (kt < 8) { Xb = sA + kt * 32;       strd = 256; }
        else        { Xb = sS + (kt - 8) * 32; strd = 128; }
        #pragma unroll 8
        for (int kk = 0; kk < 32; ++kk) {
            float xv[8];
            #pragma unroll
            for (int ii = 0; ii < 8; ++ii) xv[ii] = Xb[(nBase + ii) * strd + kk];
            float4 w0 = *reinterpret_cast<const float4*>(&sW[kk * 256 + j0]);
            float4 w1 = *reinterpret_cast<const float4*>(&sW[kk * 256 + j0 + 4]);
            float wv[8] = {w0.x, w0.y, w0.z, w0.w, w1.x, w1.y, w1.z, w1.w};
            #pragma unroll
            for (int ii = 0; ii < 8; ++ii)
                #pragma unroll
                for (int jj = 0; jj < 8; ++jj)
                    acc[ii][jj] = fmaf(xv[ii], wv[jj], acc[ii][jj]);
        }
    }
    #pragma unroll
    for (int ii = 0; ii < 8; ++ii) {
        float4 h0 = make_float4(fmaxf(acc[ii][0], 0.f), fmaxf(acc[ii][1], 0.f),
                                fmaxf(acc[ii][2], 0.f), fmaxf(acc[ii][3], 0.f));
        float4 h1 = make_float4(fmaxf(acc[ii][4], 0.f), fmaxf(acc[ii][5], 0.f),
                                fmaxf(acc[ii][6], 0.f), fmaxf(acc[ii][7], 0.f));
        *reinterpret_cast<float4*>(&sH[(nBase + ii) * 256 + j0])     = h0;
        *reinterpret_cast<float4*>(&sH[(nBase + ii) * 256 + j0 + 4]) = h1;
    }

    const int j4 = lane * 4;
    float acc2[8][4];
    #pragma unroll
    for (int jj = 0; jj < 4; ++jj) {
        float bv = bn2[j4 + jj];
        #pragma unroll
        for (int ii = 0; ii < 8; ++ii) acc2[ii][jj] = bv;
    }
    for (int kt = 0; kt < 8; ++kt) {
        __syncthreads();
        {
            const float4* src = reinterpret_cast<const float4*>(Wn2 + kt * 32 * 128);
            float4* dw = reinterpret_cast<float4*>(sW);
            #pragma unroll
            for (int t0 = 0; t0 < 4; ++t0) dw[tid + t0 * 256] = src[tid + t0 * 256];
        }
        __syncthreads();
        #pragma unroll 8
        for (int kk = 0; kk < 32; ++kk) {
            float xv[8];
            #pragma unroll
            for (int ii = 0; ii < 8; ++ii) xv[ii] = sH[(nBase + ii) * 256 + kt * 32 + kk];
            float4 w = *reinterpret_cast<const float4*>(&sW[kk * 128 + j4]);
            float wv[4] = {w.x, w.y, w.z, w.w};
            #pragma unroll
            for (int ii = 0; ii < 8; ++ii)
                #pragma unroll
                for (int jj = 0; jj < 4; ++jj)
                    acc2[ii][jj] = fmaf(xv[ii], wv[jj], acc2[ii][jj]);
        }
    }
    #pragma unroll
    for (int ii = 0; ii < 8; ++ii) {
        int n = n0 + nBase + ii;
        if (n < N) {
            float4 s = *reinterpret_cast<const float4*>(&sS[(nBase + ii) * 128 + j4]);
            float4 o = make_float4(s.x + acc2[ii][0], s.y + acc2[ii][1],
                                   s.z + acc2[ii][2], s.w + acc2[ii][3]);
            *reinterpret_cast<float4*>(&out[(size_t)n * 128 + j4]) = o;
        }
    }
}

// ---------------------------------------------------------------------------
extern "C" void kernel_launch(void* const* d_in, const int* in_sizes, int n_in,
                              void* d_out, int out_size)
{
    const float* node_states = (const float*)d_in[0];
    const float* edge_feat   = (const float*)d_in[1];
    const int*   from_idx    = (const int*)d_in[2];
    const int*   to_idx      = (const int*)d_in[3];
    const float* W1  = (const float*)d_in[4];
    const float* b1  = (const float*)d_in[5];
    const float* W2  = (const float*)d_in[6];
    const float* b2  = (const float*)d_in[7];
    const float* RW1 = (const float*)d_in[8];
    const float* Rb1 = (const float*)d_in[9];
    const float* RW2 = (const float*)d_in[10];
    const float* Rb2 = (const float*)d_in[11];
    const float* Wn1 = (const float*)d_in[12];
    const float* bn1 = (const float*)d_in[13];
    const float* Wn2 = (const float*)d_in[14];
    const float* bn2 = (const float*)d_in[15];
    float* out = (float*)d_out;

    const int N = in_sizes[0] / 128;
    const int E = in_sizes[2];

    __half* w2p;
    cudaGetSymbolAddress((void**)&w2p, g_w2);

    cudaFuncSetAttribute(edge_mma_kernel, cudaFuncAttributeMaxDynamicSharedMemorySize, ESMEM);
    cudaFuncSetAttribute(precompute_y, cudaFuncAttributeMaxDynamicSharedMemorySize, 16384 * 4);
    cudaFuncSetAttribute(node_kernel, cudaFuncAttributeMaxDynamicSharedMemorySize, 49152 * 4);

    // CSR prologue
    zero_cnt_kernel<<<(N + 255) / 256, 256>>>(N);
    hist_kernel<<<(2 * E + 255) / 256, 256>>>(to_idx, from_idx, E);
    scan_kernel<<<1, 1024>>>(N);
    perm_kernel<<<(2 * E + 255) / 256, 256>>>(to_idx, from_idx, E);

    prep_w_kernel<<<256, 256>>>(W2,  w2p);
    prep_w_kernel<<<256, 256>>>(RW2, w2p + 65536);
    precompute_y<<<(N + 63) / 64, 256, 16384 * 4>>>(node_states, W1, RW1, b1, Rb1, N);
    edge_mma_kernel<<<(E + 127) / 128, 512, ESMEM>>>(
        edge_feat, from_idx, to_idx, W1, RW1, b2, Rb2, E);
    gather_kernel<<<(N + 63) / 64, 512>>>(N);
    node_kernel<<<(N + 63) / 64, 256, 49152 * 4>>>(node_states, Wn1, bn1, Wn2, bn2, out, N);
}

// round 15
// speedup vs baseline: 1.1903x; 1.1903x over previous
#include <cuda_runtime.h>
#include <cuda_fp16.h>
#include <cstdint>

#define MAX_N 50000

// ---------------- device scratch (no allocation allowed) -------------------
// g_Yh row layout (1024 halfs): [Y0 | Y3 | Y1 | Y2]
//   fwd edge: Y0[f] + Y1[t];  rev edge: Y2[t] + Y3[f]   (biases folded)
__device__ __half g_Yh[(size_t)MAX_N * 1024];  // 102.4 MB, fits L2
__device__ float  g_agg[(size_t)MAX_N * 256];  // [N][256] aggregation
__device__ __half g_w2[2][65536];              // [dir][n*256+k] fp16 W2

// ---------------- small asm helpers ----------------------------------------
__device__ __forceinline__ uint32_t smem_u32(const void* p) {
    uint32_t a;
    asm("{ .reg .u64 t; cvta.to.shared.u64 t, %1; cvt.u32.u64 %0, t; }" : "=r"(a) : "l"(p));
    return a;
}
__device__ __forceinline__ void cpa16(uint32_t dst, const void* src) {
    asm volatile("cp.async.cg.shared.global [%0], [%1], 16;" :: "r"(dst), "l"(src));
}
#define CP_COMMIT() asm volatile("cp.async.commit_group;" ::: "memory")
#define CP_WAIT(n)  asm volatile("cp.async.wait_group %0;" :: "n"(n) : "memory")

__device__ __forceinline__ void ldsm4(uint32_t* r, uint32_t addr) {
    asm volatile("ldmatrix.sync.aligned.m8n8.x4.shared.b16 {%0,%1,%2,%3}, [%4];"
                 : "=r"(r[0]), "=r"(r[1]), "=r"(r[2]), "=r"(r[3]) : "r"(addr));
}
__device__ __forceinline__ void ldsm2(uint32_t* r, uint32_t addr) {
    asm volatile("ldmatrix.sync.aligned.m8n8.x2.shared.b16 {%0,%1}, [%2];"
                 : "=r"(r[0]), "=r"(r[1]) : "r"(addr));
}
__device__ __forceinline__ void mma16816(float* c, const uint32_t* a, const uint32_t* b) {
    asm volatile("mma.sync.aligned.m16n8k16.row.col.f32.f16.f16.f32 "
                 "{%0,%1,%2,%3}, {%4,%5,%6,%7}, {%8,%9}, {%0,%1,%2,%3};"
                 : "+f"(c[0]), "+f"(c[1]), "+f"(c[2]), "+f"(c[3])
                 : "r"(a[0]), "r"(a[1]), "r"(a[2]), "r"(a[3]), "r"(b[0]), "r"(b[1]));
}
__device__ __forceinline__ void red2(float* p, float x, float y) {
    asm volatile("red.global.add.v2.f32 [%0], {%1,%2};" :: "l"(p), "f"(x), "f"(y) : "memory");
}
__device__ __forceinline__ uint32_t f2h(float a, float b) {
    __half2 h = __floats2half2_rn(a, b);
    return *reinterpret_cast<uint32_t*>(&h);
}
// combine: relu(a + b + ef*w) in half2
__device__ __forceinline__ uint32_t cmb(uint32_t a, uint32_t b, uint32_t w, __half2 ef2) {
    __half2 s = __hadd2(*reinterpret_cast<__half2*>(&a), *reinterpret_cast<__half2*>(&b));
    s = __hfma2(ef2, *reinterpret_cast<__half2*>(&w), s);
    __half2 z = __floats2half2_rn(0.f, 0.f);
    s = __hmax2(s, z);
    return *reinterpret_cast<uint32_t*>(&s);
}

// ---------------- edge-kernel smem layout (byte offsets) --------------------
#define SH    0            // [128 rows][264 halfs] hidden (stride 528B) = 67,584B
#define SWB   67584        // 2 stages x [256 n][72 halfs] = 2 x 36,864B -> 141,312
#define SBIAS 141312       // 256 f32 -> 142,336
#define SWEFH 142336       // 256 half -> 142,848
#define SEF   142848       // 128 f32 -> 143,360
#define ESMEM 143360

// ---------------- prep: W2 transpose + fp16 round ---------------------------
__global__ void prep_w_kernel(const float* __restrict__ W, __half* __restrict__ oh) {
    int i = blockIdx.x * 256 + threadIdx.x;      // i = n*256 + k
    if (i >= 65536) return;
    int n = i >> 8, k = i & 255;
    oh[i] = __float2half_rn(W[k * 256 + n]);
}

__global__ void zero_agg_kernel(int n4) {
    float4* p = reinterpret_cast<float4*>(g_agg);
    int i = blockIdx.x * blockDim.x + threadIdx.x;
    int stride = gridDim.x * blockDim.x;
    float4 z = make_float4(0.f, 0.f, 0.f, 0.f);
    for (; i < n4; i += stride) p[i] = z;
}

// ---------------- node-level L1 precompute (exact fp32 FFMA -> fp16) --------
// 256 threads, 8x8 tiles; (256,2) caps regs at 128 -> 2 CTAs/SM.
__global__ __launch_bounds__(256, 2)
void precompute_y(const float* __restrict__ ns,
                  const float* __restrict__ W1, const float* __restrict__ RW1,
                  const float* __restrict__ b1, const float* __restrict__ Rb1, int N)
{
    extern __shared__ float sm[];
    float* sS = sm;           // 64*128
    float* sW = sm + 8192;    // 32*256
    const int tid = threadIdx.x;
    const int n0 = blockIdx.x * 64;

    for (int t = tid; t < 64 * 32; t += 256) {
        int n = t >> 5, c = t & 31;
        float4 v = make_float4(0.f, 0.f, 0.f, 0.f);
        if (n0 + n < N)
            v = reinterpret_cast<const float4*>(ns)[(size_t)(n0 + n) * 32 + c];
        reinterpret_cast<float4*>(sS)[t] = v;
    }

    const int wg = tid >> 5, lane = tid & 31;
    const int nb = wg * 8, j0 = lane * 8;

    for (int q = 0; q < 4; ++q) {
        const float* Wsrc = (q < 2) ? W1 : RW1;
        const int rowoff = (q & 1) * 128;
        const int seg = (q == 0) ? 0 : (q == 1) ? 2 : (q == 2) ? 3 : 1;
        float acc[8][8];
        #pragma unroll
        for (int jj = 0; jj < 8; ++jj) {
            float bv = (q == 1) ? b1[j0 + jj] : ((q == 3) ? Rb1[j0 + jj] : 0.f);
            #pragma unroll
            for (int ii = 0; ii < 8; ++ii) acc[ii][jj] = bv;
        }
        for (int kt = 0; kt < 4; ++kt) {
            __syncthreads();
            {
                const float4* src = reinterpret_cast<const float4*>(Wsrc + (rowoff + kt * 32) * 256);
                float4* dw = reinterpret_cast<float4*>(sW);
                #pragma unroll
                for (int t0 = 0; t0 < 8; ++t0) dw[tid + t0 * 256] = src[tid + t0 * 256];
            }
            __syncthreads();
            #pragma unroll 8
            for (int kk = 0; kk < 32; ++kk) {
                float xv[8];
                #pragma unroll
                for (int ii = 0; ii < 8; ++ii) xv[ii] = sS[(nb + ii) * 128 + kt * 32 + kk];
                float4 w0 = *reinterpret_cast<const float4*>(&sW[kk * 256 + j0]);
                float4 w1 = *reinterpret_cast<const float4*>(&sW[kk * 256 + j0 + 4]);
                float wv[8] = {w0.x, w0.y, w0.z, w0.w, w1.x, w1.y, w1.z, w1.w};
                #pragma unroll
                for (int ii = 0; ii < 8; ++ii)
                    #pragma unroll
                    for (int jj = 0; jj < 8; ++jj)
                        acc[ii][jj] = fmaf(xv[ii], wv[jj], acc[ii][jj]);
            }
        }
        #pragma unroll
        for (int ii = 0; ii < 8; ++ii) {
            int n = n0 + nb + ii;
            if (n < N) {
                uint4 pk;
                pk.x = f2h(acc[ii][0], acc[ii][1]);
                pk.y = f2h(acc[ii][2], acc[ii][3]);
                pk.z = f2h(acc[ii][4], acc[ii][5]);
                pk.w = f2h(acc[ii][6], acc[ii][7]);
                *reinterpret_cast<uint4*>(g_Yh + (size_t)n * 1024 + seg * 256 + j0) = pk;
            }
        }
    }
}

// ---------------- L2 GEMM: single-term fp16, 64-k chunks (fewer barriers) ---
// Stage layout: [256 n][72 halfs] (row stride 144B, bank-offset 4 per n row).
__device__ __forceinline__ void gemm_l2(const __half* __restrict__ gw,
                                        uint32_t smb, int tid,
                                        uint32_t aB0, uint32_t aB1, uint32_t bB,
                                        float acc0[8][4], float acc1[8][4])
{
    auto copy_chunk = [&](int s, int c) {
        #pragma unroll
        for (int i = 0; i < 4; ++i) {
            int idx = i * 512 + tid;              // 2048 x 16B = 64KB
            int n = idx >> 3, seg = idx & 7;      // 8 segs of 8 halfs = 64 halfs
            const __half* src = gw + n * 256 + c * 64 + seg * 8;
            uint32_t dst = smb + SWB + (uint32_t)(s * 36864 + n * 144 + seg * 16);
            cpa16(dst, src);
        }
    };

    copy_chunk(0, 0);
    CP_COMMIT();
    for (int c = 0; c < 4; ++c) {
        const int s = c & 1;
        if (c < 3) { copy_chunk(s ^ 1, c + 1); CP_COMMIT(); CP_WAIT(1); }
        else       { CP_WAIT(0); }
        __syncthreads();
        #pragma unroll
        for (int ks = 0; ks < 4; ++ks) {
            const int step = c * 4 + ks;
            const uint32_t coloff = ((step < 8) ? 0u : 256u) + (step & 7) * 32;
            uint32_t A0[4], A1[4];
            ldsm4(A0, aB0 + coloff);
            ldsm4(A1, aB1 + coloff);
            const uint32_t wrow = smb + SWB + (uint32_t)(s * 36864) + bB + ks * 32;
            #pragma unroll
            for (int nf = 0; nf < 8; ++nf) {
                uint32_t Bh[2];
                ldsm2(Bh, wrow + nf * 1152);      // +8 n-rows = 8*144B
                mma16816(acc0[nf], A0, Bh);
                mma16816(acc1[nf], A1, Bh);
            }
        }
        __syncthreads();
    }
}

// ---------------- edge kernel: 128 edges/CTA, half2 combine + L2 MMA --------
__global__ __launch_bounds__(512, 1)
void edge_mma_kernel(const float* __restrict__ ef,
                     const int* __restrict__ fidx, const int* __restrict__ tidx,
                     const float* __restrict__ W1, const float* __restrict__ RW1,
                     const float* __restrict__ b2, const float* __restrict__ Rb2,
                     int E)
{
    extern __shared__ float smf[];
    char* smc = reinterpret_cast<char*>(smf);
    const uint32_t smb = smem_u32(smf);
    const int tid = threadIdx.x;
    const int wid = tid >> 5, lane = tid & 31;
    const int wm = wid & 3, wn = wid >> 2;       // 4 m-warps x 4 n-warps
    const int m0 = wm * 32, n0 = wn * 64;        // warp tile 32 x 64
    const int e0 = blockIdx.x * 128;

    float*  sBias  = reinterpret_cast<float*>(smc + SBIAS);
    __half* sWefH  = reinterpret_cast<__half*>(smc + SWEFH);
    float*  sEf    = reinterpret_cast<float*>(smc + SEF);

    if (tid < 128) sEf[tid] = (e0 + tid < E) ? ef[e0 + tid] : 0.f;

    // lane-resolved fragment addresses (A from sH, stride 264 halfs)
    const int rA = (lane & 7) + ((lane >> 3) & 1) * 8;
    const int cAo = (lane >> 4) * 8;
    const uint32_t aB0 = smb + SH + (uint32_t)((m0 + rA) * 528 + cAo * 2);
    const uint32_t aB1 = aB0 + 16 * 528;         // +16 rows
    const uint32_t bB = (uint32_t)((n0 + (lane & 7)) * 144 + ((lane >> 3) & 1) * 16);
    const int r0 = m0 + (lane >> 2);

    // combine-phase indices: 128 rows x 4 col-quarters (64 halfs each)
    const int crow = tid >> 2, cq = tid & 3;
    int ce = e0 + crow; if (ce >= E) ce = E - 1;
    const int cf = fidx[ce], ct = tidx[ce];

    for (int dir = 0; dir < 2; ++dir) {
        const float* bias2 = dir ? Rb2 : b2;
        const float* wef = (dir ? RW1 : W1) + 65536;    // W1 row k=256 (ef col)
        const __half* gw = g_w2[dir];

        __syncthreads();                          // prior dir's smem readers done
        if (tid < 256) {
            sBias[tid] = bias2[tid];
            sWefH[tid] = __float2half_rn(wef[tid]);
        }
        __syncthreads();

        // ---- L1 combine (half2): h = relu(Ya + Yb + ef*wef) -> sH -----------
        {
            const __half* Ap;
            const __half* Bp;
            if (dir == 0) {   // fwd: Y0[f] + Y1[t]
                Ap = g_Yh + (size_t)cf * 1024 + cq * 64;
                Bp = g_Yh + (size_t)ct * 1024 + 512 + cq * 64;
            } else {          // rev: Y2[t] + Y3[f]
                Ap = g_Yh + (size_t)ct * 1024 + 768 + cq * 64;
                Bp = g_Yh + (size_t)cf * 1024 + 256 + cq * 64;
            }
            const __half2 ef2 = __float2half2_rn(sEf[crow]);
            const uint4* A4 = reinterpret_cast<const uint4*>(Ap);
            const uint4* B4 = reinterpret_cast<const uint4*>(Bp);
            const uint4* W4 = reinterpret_cast<const uint4*>(sWefH + cq * 64);
            #pragma unroll
            for (int i = 0; i < 8; ++i) {
                uint4 ua = A4[i], ub = B4[i], uw = W4[i];
                uint4 pk;
                pk.x = cmb(ua.x, ub.x, uw.x, ef2);
                pk.y = cmb(ua.y, ub.y, uw.y, ef2);
                pk.z = cmb(ua.z, ub.z, uw.z, ef2);
                pk.w = cmb(ua.w, ub.w, uw.w, ef2);
                *reinterpret_cast<uint4*>(smc + SH + crow * 528 + (cq * 64 + i * 8) * 2) = pk;
            }
        }
        __syncthreads();                          // sH visible to ldmatrix

        // ---- L2: msg = h @ W2 + b2 (single-term fp16 HMMA) ------------------
        float acc0[8][4], acc1[8][4];
        #pragma unroll
        for (int nf = 0; nf < 8; ++nf) {
            int cc = n0 + nf * 8 + (lane & 3) * 2;
            float bv0 = sBias[cc], bv1 = sBias[cc + 1];
            acc0[nf][0] = bv0; acc0[nf][1] = bv1;
            acc0[nf][2] = bv0; acc0[nf][3] = bv1;
            acc1[nf][0] = bv0; acc1[nf][1] = bv1;
            acc1[nf][2] = bv0; acc1[nf][3] = bv1;
        }
        gemm_l2(gw, smb, tid, aB0, aB1, bB, acc0, acc1);

        // ---- scatter: red.v2 straight from accumulators ---------------------
        {
            const int* iD = dir ? fidx : tidx;
            const int e00 = e0 + r0;
            const int e08 = e00 + 8, e16 = e00 + 16, e24 = e00 + 24;
            const int d00 = (e00 < E) ? iD[e00] : 0;
            const int d08 = (e08 < E) ? iD[e08] : 0;
            const int d16 = (e16 < E) ? iD[e16] : 0;
            const int d24 = (e24 < E) ? iD[e24] : 0;
            float* p00 = g_agg + (size_t)d00 * 256;
            float* p08 = g_agg + (size_t)d08 * 256;
            float* p16 = g_agg + (size_t)d16 * 256;
            float* p24 = g_agg + (size_t)d24 * 256;
            #pragma unroll
            for (int nf = 0; nf < 8; ++nf) {
                int cc = n0 + nf * 8 + (lane & 3) * 2;
                if (e00 < E) red2(p00 + cc, acc0[nf][0], acc0[nf][1]);
                if (e08 < E) red2(p08 + cc, acc0[nf][2], acc0[nf][3]);
                if (e16 < E) red2(p16 + cc, acc1[nf][0], acc1[nf][1]);
                if (e24 < E) red2(p24 + cc, acc1[nf][2], acc1[nf][3]);
            }
        }
        __syncthreads();                          // all sH reads done before next combine
    }
}

// ---------------- node update MLP + residual (FFMA, proven 256-thr) --------
__global__ __launch_bounds__(256, 1)
void node_kernel(const float* __restrict__ node_states,
                 const float* __restrict__ Wn1, const float* __restrict__ bn1,
                 const float* __restrict__ Wn2, const float* __restrict__ bn2,
                 float* __restrict__ out, int N)
{
    extern __shared__ float sm[];
    float* sA = sm;            // 64*256
    float* sS = sm + 16384;    // 64*128
    float* sH = sm + 24576;    // 64*256
    float* sW = sm + 40960;    // 32*256

    const int tid = threadIdx.x;
    const int n0  = blockIdx.x * 64;

    for (int t = tid; t < 64 * 64; t += 256) {
        int n = t >> 6, c = t & 63;
        float4 v = make_float4(0.f, 0.f, 0.f, 0.f);
        if (n0 + n < N)
            v = reinterpret_cast<const float4*>(g_agg)[(size_t)(n0 + n) * 64 + c];
        reinterpret_cast<float4*>(sA)[t] = v;
    }
    for (int t = tid; t < 64 * 32; t += 256) {
        int n = t >> 5, c = t & 31;
        float4 v = make_float4(0.f, 0.f, 0.f, 0.f);
        if (n0 + n < N)
            v = reinterpret_cast<const float4*>(node_states)[(size_t)(n0 + n) * 32 + c];
        reinterpret_cast<float4*>(sS)[t] = v;
    }
    __syncthreads();

    const int wg = tid >> 5, lane = tid & 31;
    const int nBase = wg * 8, j0 = lane * 8;

    float acc[8][8];
    #pragma unroll
    for (int jj = 0; jj < 8; ++jj) {
        float bv = bn1[j0 + jj];
        #pragma unroll
        for (int ii = 0; ii < 8; ++ii) acc[ii][jj] = bv;
    }
    for (int kt = 0; kt < 12; ++kt) {
        __syncthreads();
        {
            const float4* src = reinterpret_cast<const float4*>(Wn1 + kt * 32 * 256);
            float4* dw = reinterpret_cast<float4*>(sW);
            #pragma unroll
            for (int t0 = 0; t0 < 8; ++t0) dw[tid + t0 * 256] = src[tid + t0 * 256];
        }
        __syncthreads();
        const float* Xb; int strd;
        if (kt < 8) { Xb = sA + kt * 32;       strd = 256; }
        else        { Xb = sS + (kt - 8) * 32; strd = 128; }
        #pragma unroll 8
        for (int kk = 0; kk < 32; ++kk) {
            float xv[8];
            #pragma unroll
            for (int ii = 0; ii < 8; ++ii) xv[ii] = Xb[(nBase + ii) * strd + kk];
            float4 w0 = *reinterpret_cast<const float4*>(&sW[kk * 256 + j0]);
            float4 w1 = *reinterpret_cast<const float4*>(&sW[kk * 256 + j0 + 4]);
            float wv[8] = {w0.x, w0.y, w0.z, w0.w, w1.x, w1.y, w1.z, w1.w};
            #pragma unroll
            for (int ii = 0; ii < 8; ++ii)
                #pragma unroll
                for (int jj = 0; jj < 8; ++jj)
                    acc[ii][jj] = fmaf(xv[ii], wv[jj], acc[ii][jj]);
        }
    }
    #pragma unroll
    for (int ii = 0; ii < 8; ++ii) {
        float4 h0 = make_float4(fmaxf(acc[ii][0], 0.f), fmaxf(acc[ii][1], 0.f),
                                fmaxf(acc[ii][2], 0.f), fmaxf(acc[ii][3], 0.f));
        float4 h1 = make_float4(fmaxf(acc[ii][4], 0.f), fmaxf(acc[ii][5], 0.f),
                                fmaxf(acc[ii][6], 0.f), fmaxf(acc[ii][7], 0.f));
        *reinterpret_cast<float4*>(&sH[(nBase + ii) * 256 + j0])     = h0;
        *reinterpret_cast<float4*>(&sH[(nBase + ii) * 256 + j0 + 4]) = h1;
    }

    const int j4 = lane * 4;
    float acc2[8][4];
    #pragma unroll
    for (int jj = 0; jj < 4; ++jj) {
        float bv = bn2[j4 + jj];
        #pragma unroll
        for (int ii = 0; ii < 8; ++ii) acc2[ii][jj] = bv;
    }
    for (int kt = 0; kt < 8; ++kt) {
        __syncthreads();
        {
            const float4* src = reinterpret_cast<const float4*>(Wn2 + kt * 32 * 128);
            float4* dw = reinterpret_cast<float4*>(sW);
            #pragma unroll
            for (int t0 = 0; t0 < 4; ++t0) dw[tid + t0 * 256] = src[tid + t0 * 256];
        }
        __syncthreads();
        #pragma unroll 8
        for (int kk = 0; kk < 32; ++kk) {
            float xv[8];
            #pragma unroll
            for (int ii = 0; ii < 8; ++ii) xv[ii] = sH[(nBase + ii) * 256 + kt * 32 + kk];
            float4 w = *reinterpret_cast<const float4*>(&sW[kk * 128 + j4]);
            float wv[4] = {w.x, w.y, w.z, w.w};
            #pragma unroll
            for (int ii = 0; ii < 8; ++ii)
                #pragma unroll
                for (int jj = 0; jj < 4; ++jj)
                    acc2[ii][jj] = fmaf(xv[ii], wv[jj], acc2[ii][jj]);
        }
    }
    #pragma unroll
    for (int ii = 0; ii < 8; ++ii) {
        int n = n0 + nBase + ii;
        if (n < N) {
            float4 s = *reinterpret_cast<const float4*>(&sS[(nBase + ii) * 128 + j4]);
            float4 o = make_float4(s.x + acc2[ii][0], s.y + acc2[ii][1],
                                   s.z + acc2[ii][2], s.w + acc2[ii][3]);
            *reinterpret_cast<float4*>(&out[(size_t)n * 128 + j4]) = o;
        }
    }
}

// ---------------------------------------------------------------------------
extern "C" void kernel_launch(void* const* d_in, const int* in_sizes, int n_in,
                              void* d_out, int out_size)
{
    const float* node_states = (const float*)d_in[0];
    const float* edge_feat   = (const float*)d_in[1];
    const int*   from_idx    = (const int*)d_in[2];
    const int*   to_idx      = (const int*)d_in[3];
    const float* W1  = (const float*)d_in[4];
    const float* b1  = (const float*)d_in[5];
    const float* W2  = (const float*)d_in[6];
    const float* b2  = (const float*)d_in[7];
    const float* RW1 = (const float*)d_in[8];
    const float* Rb1 = (const float*)d_in[9];
    const float* RW2 = (const float*)d_in[10];
    const float* Rb2 = (const float*)d_in[11];
    const float* Wn1 = (const float*)d_in[12];
    const float* bn1 = (const float*)d_in[13];
    const float* Wn2 = (const float*)d_in[14];
    const float* bn2 = (const float*)d_in[15];
    float* out = (float*)d_out;

    const int N = in_sizes[0] / 128;
    const int E = in_sizes[2];

    __half* w2p;
    cudaGetSymbolAddress((void**)&w2p, g_w2);

    cudaFuncSetAttribute(edge_mma_kernel, cudaFuncAttributeMaxDynamicSharedMemorySize, ESMEM);
    cudaFuncSetAttribute(precompute_y, cudaFuncAttributeMaxDynamicSharedMemorySize, 16384 * 4);
    cudaFuncSetAttribute(node_kernel, cudaFuncAttributeMaxDynamicSharedMemorySize, 49152 * 4);

    zero_agg_kernel<<<1024, 256>>>(N * 64);
    prep_w_kernel<<<256, 256>>>(W2,  w2p);
    prep_w_kernel<<<256, 256>>>(RW2, w2p + 65536);
    precompute_y<<<(N + 63) / 64, 256, 16384 * 4>>>(node_states, W1, RW1, b1, Rb1, N);
    edge_mma_kernel<<<(E + 127) / 128, 512, ESMEM>>>(
        edge_feat, from_idx, to_idx, W1, RW1, b2, Rb2, E);
    node_kernel<<<(N + 63) / 64, 256, 49152 * 4>>>(node_states, Wn1, bn1, Wn2, bn2, out, N);
}